// round 15
// baseline (speedup 1.0000x reference)
#include <cuda_runtime.h>

// Problem constants
#define TT     2048
#define CELLS  2048
#define NSEG   128
#define SEGLEN (TT / NSEG)    // 16
#define CHUNK  16             // == SEGLEN: one boundary per chunk
#define NCHUNK (TT / CHUNK)   // 128
#define PFDIST 6              // L2-prefetch distance in chunks (96 iters)

// Scratch: boundary states entering each segment (seg 1..NSEG-1).
__device__ float2 g_bound[NSEG * CELLS];

// ---------------------------------------------------------------------------
// Pass 1: serial boundary scan. 1 thread/cell, 64 blocks x 32 threads
// (one warp per SM, exclusive SMSP). 4-stage rotating register prefetch
// (48 outstanding LDGs — at the ~55/warp cap) covers L2-hit latency; an
// additional prefetch.global.L2 per iteration, PFDIST chunks ahead, pulls
// lines from DRAM into L2 without consuming scoreboard slots or registers,
// so the LDGs find L2 hits. Replaces round-13's 9.7us warm kernel.
// S1 chain: S1' = max( fma(S1, c1 - E/smax, P), max(fma(S1, c1, P - E), 0) )
// S2 as U = S2/k2: U' = fma(U, c2, S1_old); clamp provably inactive in-scan.
// ---------------------------------------------------------------------------
__global__ __launch_bounds__(32, 1)
void pass1_kernel(const float2* __restrict__ F2,   // forcings [T, CELLS]
                  const float2* __restrict__ S02,  // initial states [CELLS]
                  const float4* __restrict__ P4)   // params [CELLS]
{
    const int cell = blockIdx.x * 32 + threadIdx.x;

    const float4 u = P4[cell];
    const float smax = 10.0f  + 490.0f  * u.x;
    const float k1   = 0.01f  + 0.89f   * u.y;
    const float k2   = 0.001f + 0.199f  * u.z;
    const float kb   = 0.001f + 0.099f  * u.w;

    const float inv  = 1.0f / smax;
    const float ninv = -inv;
    const float c1   = 1.0f - k1 - k2;
    const float c2   = 1.0f - kb;

    float2 s = S02[cell];
    float S1 = s.x;
    float U  = s.y / k2;          // S2 = k2 * U

    const float2* __restrict__ F = F2 + cell;

#define LOADC(buf, ci)                                           \
    do {                                                         \
        const float2* Fp = F + (size_t)(ci) * CHUNK * CELLS;     \
        _Pragma("unroll")                                        \
        for (int i = 0; i < CHUNK; i++)                          \
            (buf)[i] = Fp[i * CELLS];                            \
    } while (0)

    // Process chunk pci while (a) issuing LDGs for chunk lci and (b) issuing
    // L2 prefetches for chunk pci+PFDIST. Tail indices clamped (redundant).
#define PROC_LOAD(pbuf, pci, lbuf, lci_raw)                      \
    do {                                                         \
        const int lci = ((lci_raw) < NCHUNK) ? (lci_raw)         \
                                             : (NCHUNK - 1);     \
        const int pfi = ((pci) + PFDIST < NCHUNK)                \
                            ? (pci) + PFDIST : (NCHUNK - 1);     \
        const float2* Fp  = F + (size_t)lci * CHUNK * CELLS;     \
        const float2* Fpf = F + (size_t)pfi * CHUNK * CELLS;     \
        _Pragma("unroll")                                        \
        for (int i = 0; i < CHUNK; i++) {                        \
            asm volatile("prefetch.global.L2 [%0];"              \
                         :: "l"(Fpf + i * CELLS));               \
            (lbuf)[i] = Fp[i * CELLS];                           \
            const float Pf  = (pbuf)[i].x;                       \
            const float Ef  = (pbuf)[i].y;                       \
            const float caa = fmaf(ninv, Ef, c1);                \
            const float pme = Pf - Ef;                           \
            const float t1  = fmaf(S1, caa, Pf);                 \
            const float t2  = fmaf(S1, c1, pme);                 \
            U = fmaf(U, c2, S1);          /* old S1 */           \
            const float m = fmaxf(t2, 0.0f);                     \
            S1 = fmaxf(t1, m);                                   \
        }                                                        \
        if ((pci) != NCHUNK - 1)                                 \
            g_bound[((pci) + 1) * CELLS + cell] =                \
                make_float2(S1, k2 * U);                         \
    } while (0)

    float2 bufA[CHUNK], bufB[CHUNK], bufC[CHUNK], bufD[CHUNK];

    LOADC(bufA, 0);
    LOADC(bufB, 1);
    LOADC(bufC, 2);

#pragma unroll 1
    for (int c = 0; c < NCHUNK; c += 4) {
        PROC_LOAD(bufA, c,     bufD, c + 3);
        PROC_LOAD(bufB, c + 1, bufA, c + 4);
        PROC_LOAD(bufC, c + 2, bufB, c + 5);
        PROC_LOAD(bufD, c + 3, bufC, c + 6);
    }
#undef LOADC
#undef PROC_LOAD
}

// ---------------------------------------------------------------------------
// Pass 2: parallel segment replay. One thread = (cell, segment).
// Replays SEGLEN steps from the boundary state, writing fluxes AND states
// with reference-faithful arithmetic. At its memory roofline (~21us).
// ---------------------------------------------------------------------------
__global__ __launch_bounds__(256)
void pass2_kernel(const float2* __restrict__ F2,   // forcings [T, CELLS]
                  const float2* __restrict__ S02,  // initial states [CELLS]
                  const float4* __restrict__ P4,   // params [CELLS]
                  float4* __restrict__ FX4,        // fluxes [T, CELLS]
                  float2* __restrict__ ST2)        // states [T, CELLS]
{
    const int cell = blockIdx.x * 256 + threadIdx.x;
    const int seg  = blockIdx.y;
    const int t0   = seg * SEGLEN;

    const float4 u = P4[cell];
    const float smax = 10.0f  + 490.0f  * u.x;
    const float k1   = 0.01f  + 0.89f   * u.y;
    const float k2   = 0.001f + 0.199f  * u.z;
    const float kb   = 0.001f + 0.099f  * u.w;
    const float inv  = 1.0f / smax;

    float2 s = (seg == 0) ? S02[cell] : g_bound[seg * CELLS + cell];
    float S1 = s.x, S2 = s.y;

    const float2* __restrict__ F  = F2  + (size_t)t0 * CELLS + cell;
    float4*       __restrict__ FX = FX4 + (size_t)t0 * CELLS + cell;
    float2*       __restrict__ ST = ST2 + (size_t)t0 * CELLS + cell;

#pragma unroll 8
    for (int i = 0; i < SEGLEN; i++) {
        const float2 f  = F[i * CELLS];
        const float P   = f.x;
        const float PET = f.y;

        const float frac = fminf(S1 * inv, 1.0f);   // S1 >= 0 always
        const float et   = PET * frac;
        const float q1   = k1 * S1;
        const float perc = k2 * S1;
        const float qb   = kb * S2;

        FX[i * CELLS] = make_float4(et, q1, perc, qb);

        S1 = fmaxf(S1 + P - et - q1 - perc, 0.0f);
        S2 = fmaxf(S2 + perc - qb, 0.0f);

        ST[i * CELLS] = make_float2(S1, S2);
    }
}

extern "C" void kernel_launch(void* const* d_in, const int* in_sizes, int n_in,
                              void* d_out, int out_size)
{
    const float* forcings = (const float*)d_in[0];   // [T,B,H,2]
    const float* states0  = (const float*)d_in[1];   // [B,H,2]
    const float* params   = (const float*)d_in[2];   // [B,H,4]

    float* out = (float*)d_out;
    float* fluxes_out = out;                                   // [T,B,H,4]
    float* states_out = out + (size_t)TT * CELLS * 4;          // [T,B,H,2]

    pass1_kernel<<<CELLS / 32, 32>>>(
        reinterpret_cast<const float2*>(forcings),
        reinterpret_cast<const float2*>(states0),
        reinterpret_cast<const float4*>(params));

    pass2_kernel<<<dim3(CELLS / 256, NSEG), 256>>>(
        reinterpret_cast<const float2*>(forcings),
        reinterpret_cast<const float2*>(states0),
        reinterpret_cast<const float4*>(params),
        reinterpret_cast<float4*>(fluxes_out),
        reinterpret_cast<float2*>(states_out));
}

// round 16
// speedup vs baseline: 1.1199x; 1.1199x over previous
#include <cuda_runtime.h>

// Problem constants
#define TT     2048
#define CELLS  2048
#define NSEG   128
#define SEGLEN (TT / NSEG)    // 16
#define CHUNK  16             // == SEGLEN: one boundary per chunk
#define NCHUNK (TT / CHUNK)   // 128

// Scratch: boundary states entering each segment (seg 1..NSEG-1).
__device__ float2 g_bound[NSEG * CELLS];
// DCE sink for the warm kernel (never actually written).
__device__ float g_sink;

// ---------------------------------------------------------------------------
// Warm kernel: stream all forcings (32 MiB) through L2. Runs CONCURRENTLY
// with pass1 on a second stream: pass1 has no data dependency on it (it only
// shortens pass1's load latency from DRAM ~1050cyc to L2 ~430cyc, which the
// 48-iteration register prefetch pipeline fully covers). Warm sweeps ~3x
// faster than pass1 consumes, so it stays ahead of pass1's read cursor.
// ---------------------------------------------------------------------------
__global__ __launch_bounds__(256)
void warm_kernel(const float4* __restrict__ F4)   // TT*CELLS*2/4 float4s
{
    const int n = TT * CELLS * 2 / 4;             // 2,097,152 float4
    float a0 = 0.0f, a1 = 0.0f;
    int i = blockIdx.x * 512 + threadIdx.x;
    const int stride = gridDim.x * 512;
#pragma unroll 2
    for (; i + 256 < n; i += stride) {
        const float4 v0 = F4[i];
        const float4 v1 = F4[i + 256];
        a0 += v0.x + v0.y + v0.z + v0.w;
        a1 += v1.x + v1.y + v1.z + v1.w;
    }
    if (i < n) {
        const float4 v = F4[i];
        a0 += v.x + v.y + v.z + v.w;
    }
    if (a0 + a1 == -1.0f) g_sink = a0;   // never true: forcings >= 0
}

// ---------------------------------------------------------------------------
// Pass 1: serial boundary scan. 1 thread/cell, 64 blocks x 32 threads
// (one warp per SM, exclusive SMSP). 4-stage rotating register prefetch
// (48 outstanding LDGs — at the ~55/warp cap), one LDG interleaved per step;
// loads hit L2 thanks to the concurrent warm sweep.
// S1 chain: S1' = max( fma(S1, c1 - E/smax, P), max(fma(S1, c1, P - E), 0) )
// S2 as U = S2/k2: U' = fma(U, c2, S1_old); clamp provably inactive in-scan.
// ---------------------------------------------------------------------------
__global__ __launch_bounds__(32, 1)
void pass1_kernel(const float2* __restrict__ F2,   // forcings [T, CELLS]
                  const float2* __restrict__ S02,  // initial states [CELLS]
                  const float4* __restrict__ P4)   // params [CELLS]
{
    const int cell = blockIdx.x * 32 + threadIdx.x;

    const float4 u = P4[cell];
    const float smax = 10.0f  + 490.0f  * u.x;
    const float k1   = 0.01f  + 0.89f   * u.y;
    const float k2   = 0.001f + 0.199f  * u.z;
    const float kb   = 0.001f + 0.099f  * u.w;

    const float inv  = 1.0f / smax;
    const float ninv = -inv;
    const float c1   = 1.0f - k1 - k2;
    const float c2   = 1.0f - kb;

    float2 s = S02[cell];
    float S1 = s.x;
    float U  = s.y / k2;          // S2 = k2 * U

    const float2* __restrict__ F = F2 + cell;

#define LOADC(buf, ci)                                           \
    do {                                                         \
        const float2* Fp = F + (size_t)(ci) * CHUNK * CELLS;     \
        _Pragma("unroll")                                        \
        for (int i = 0; i < CHUNK; i++)                          \
            (buf)[i] = Fp[i * CELLS];                            \
    } while (0)

#define PROC_LOAD(pbuf, pci, lbuf, lci_raw)                      \
    do {                                                         \
        const int lci = ((lci_raw) < NCHUNK) ? (lci_raw)         \
                                             : (NCHUNK - 1);     \
        const float2* Fp = F + (size_t)lci * CHUNK * CELLS;      \
        _Pragma("unroll")                                        \
        for (int i = 0; i < CHUNK; i++) {                        \
            (lbuf)[i] = Fp[i * CELLS];                           \
            const float Pf  = (pbuf)[i].x;                       \
            const float Ef  = (pbuf)[i].y;                       \
            const float caa = fmaf(ninv, Ef, c1);                \
            const float pme = Pf - Ef;                           \
            const float t1  = fmaf(S1, caa, Pf);                 \
            const float t2  = fmaf(S1, c1, pme);                 \
            U = fmaf(U, c2, S1);          /* old S1 */           \
            const float m = fmaxf(t2, 0.0f);                     \
            S1 = fmaxf(t1, m);                                   \
        }                                                        \
        if ((pci) != NCHUNK - 1)                                 \
            g_bound[((pci) + 1) * CELLS + cell] =                \
                make_float2(S1, k2 * U);                         \
    } while (0)

    float2 bufA[CHUNK], bufB[CHUNK], bufC[CHUNK], bufD[CHUNK];

    LOADC(bufA, 0);
    LOADC(bufB, 1);
    LOADC(bufC, 2);

#pragma unroll 1
    for (int c = 0; c < NCHUNK; c += 4) {
        PROC_LOAD(bufA, c,     bufD, c + 3);
        PROC_LOAD(bufB, c + 1, bufA, c + 4);
        PROC_LOAD(bufC, c + 2, bufB, c + 5);
        PROC_LOAD(bufD, c + 3, bufC, c + 6);
    }
#undef LOADC
#undef PROC_LOAD
}

// ---------------------------------------------------------------------------
// Pass 2: parallel segment replay. One thread = (cell, segment).
// Reference-faithful arithmetic. At its memory roofline (~21us).
// ---------------------------------------------------------------------------
__global__ __launch_bounds__(256)
void pass2_kernel(const float2* __restrict__ F2,   // forcings [T, CELLS]
                  const float2* __restrict__ S02,  // initial states [CELLS]
                  const float4* __restrict__ P4,   // params [CELLS]
                  float4* __restrict__ FX4,        // fluxes [T, CELLS]
                  float2* __restrict__ ST2)        // states [T, CELLS]
{
    const int cell = blockIdx.x * 256 + threadIdx.x;
    const int seg  = blockIdx.y;
    const int t0   = seg * SEGLEN;

    const float4 u = P4[cell];
    const float smax = 10.0f  + 490.0f  * u.x;
    const float k1   = 0.01f  + 0.89f   * u.y;
    const float k2   = 0.001f + 0.199f  * u.z;
    const float kb   = 0.001f + 0.099f  * u.w;
    const float inv  = 1.0f / smax;

    float2 s = (seg == 0) ? S02[cell] : g_bound[seg * CELLS + cell];
    float S1 = s.x, S2 = s.y;

    const float2* __restrict__ F  = F2  + (size_t)t0 * CELLS + cell;
    float4*       __restrict__ FX = FX4 + (size_t)t0 * CELLS + cell;
    float2*       __restrict__ ST = ST2 + (size_t)t0 * CELLS + cell;

#pragma unroll 8
    for (int i = 0; i < SEGLEN; i++) {
        const float2 f  = F[i * CELLS];
        const float P   = f.x;
        const float PET = f.y;

        const float frac = fminf(S1 * inv, 1.0f);   // S1 >= 0 always
        const float et   = PET * frac;
        const float q1   = k1 * S1;
        const float perc = k2 * S1;
        const float qb   = kb * S2;

        FX[i * CELLS] = make_float4(et, q1, perc, qb);

        S1 = fmaxf(S1 + P - et - q1 - perc, 0.0f);
        S2 = fmaxf(S2 + perc - qb, 0.0f);

        ST[i * CELLS] = make_float2(S1, S2);
    }
}

// ---------------------------------------------------------------------------
// Overlap resources (stream + events), created once at program init.
// No device allocations. Falls back to serial warm->pass1->pass2 if needed.
// ---------------------------------------------------------------------------
namespace {
struct OverlapRes {
    cudaStream_t sB = nullptr;
    cudaEvent_t  ev0 = nullptr, evW = nullptr;
    bool ok = false;
    OverlapRes() {
        if (cudaStreamCreateWithFlags(&sB, cudaStreamNonBlocking) != cudaSuccess)
            return;
        if (cudaEventCreateWithFlags(&ev0, cudaEventDisableTiming) != cudaSuccess)
            return;
        if (cudaEventCreateWithFlags(&evW, cudaEventDisableTiming) != cudaSuccess)
            return;
        ok = true;
    }
};
OverlapRes g_res;
}

extern "C" void kernel_launch(void* const* d_in, const int* in_sizes, int n_in,
                              void* d_out, int out_size)
{
    const float* forcings = (const float*)d_in[0];   // [T,B,H,2]
    const float* states0  = (const float*)d_in[1];   // [B,H,2]
    const float* params   = (const float*)d_in[2];   // [B,H,4]

    float* out = (float*)d_out;
    float* fluxes_out = out;                                   // [T,B,H,4]
    float* states_out = out + (size_t)TT * CELLS * 4;          // [T,B,H,2]

    const float2* F2  = reinterpret_cast<const float2*>(forcings);
    const float2* S02 = reinterpret_cast<const float2*>(states0);
    const float4* P4  = reinterpret_cast<const float4*>(params);
    const float4* F4  = reinterpret_cast<const float4*>(forcings);

    if (g_res.ok) {
        // Fork: warm on stream B, concurrent with pass1 on the origin stream.
        cudaEventRecord(g_res.ev0, 0);
        cudaStreamWaitEvent(g_res.sB, g_res.ev0, 0);
        warm_kernel<<<1024, 256, 0, g_res.sB>>>(F4);
        cudaEventRecord(g_res.evW, g_res.sB);

        pass1_kernel<<<CELLS / 32, 32>>>(F2, S02, P4);

        // Join before pass2 (warm is long done by then; keeps graph well-formed).
        cudaStreamWaitEvent(0, g_res.evW, 0);
        pass2_kernel<<<dim3(CELLS / 256, NSEG), 256>>>(
            F2, S02, P4,
            reinterpret_cast<float4*>(fluxes_out),
            reinterpret_cast<float2*>(states_out));
    } else {
        // Serial fallback (round-13 behavior).
        warm_kernel<<<1024, 256>>>(F4);
        pass1_kernel<<<CELLS / 32, 32>>>(F2, S02, P4);
        pass2_kernel<<<dim3(CELLS / 256, NSEG), 256>>>(
            F2, S02, P4,
            reinterpret_cast<float4*>(fluxes_out),
            reinterpret_cast<float2*>(states_out));
    }
}

// round 17
// speedup vs baseline: 1.1587x; 1.0346x over previous
#include <cuda_runtime.h>

// Problem constants
#define TT     2048
#define CELLS  2048
#define NSEG   128
#define SEGLEN (TT / NSEG)    // 16
#define CHUNK  16             // == SEGLEN: one boundary per chunk
#define NCHUNK (TT / CHUNK)   // 128
#define WARMBLK 256           // throttled warm grid (was 1024: starved pass1)

// Scratch: boundary states entering each segment (seg 1..NSEG-1).
__device__ float2 g_bound[NSEG * CELLS];
// DCE sink for the warm kernel (never actually written).
__device__ float g_sink;

// ---------------------------------------------------------------------------
// Warm kernel: stream all forcings (32 MiB) through L2, THROTTLED to ~2-2.5
// TB/s (256 blocks) so it populates L2 ahead of pass1 without saturating the
// DRAM/LTS queues (1024 blocks at ~3.9 TB/s stalled pass1 completely during
// the warm window — round 16). Runs concurrently with pass1 on stream B.
// ---------------------------------------------------------------------------
__global__ __launch_bounds__(256)
void warm_kernel(const float4* __restrict__ F4)   // TT*CELLS*2/4 float4s
{
    const int n = TT * CELLS * 2 / 4;             // 2,097,152 float4
    const int nthr = WARMBLK * 256;               // 65,536 threads
    float a0 = 0.0f, a1 = 0.0f, a2 = 0.0f, a3 = 0.0f;
    int i = blockIdx.x * 256 + threadIdx.x;
    // n / nthr = 32 iterations; unroll 4 for MLP.
#pragma unroll 1
    for (; i + 3 * nthr < n; i += 4 * nthr) {
        const float4 v0 = F4[i];
        const float4 v1 = F4[i + nthr];
        const float4 v2 = F4[i + 2 * nthr];
        const float4 v3 = F4[i + 3 * nthr];
        a0 += v0.x + v0.y + v0.z + v0.w;
        a1 += v1.x + v1.y + v1.z + v1.w;
        a2 += v2.x + v2.y + v2.z + v2.w;
        a3 += v3.x + v3.y + v3.z + v3.w;
    }
    for (; i < n; i += nthr) {
        const float4 v = F4[i];
        a0 += v.x + v.y + v.z + v.w;
    }
    if (a0 + a1 + a2 + a3 == -1.0f) g_sink = a0;  // never true: forcings >= 0
}

// ---------------------------------------------------------------------------
// Pass 1: serial boundary scan. 1 thread/cell, 64 blocks x 32 threads
// (one warp per SM, exclusive SMSP). 4-stage rotating register prefetch
// (48 outstanding LDGs — at the ~55/warp cap), one LDG interleaved per step;
// loads hit L2 thanks to the concurrent (throttled) warm sweep.
// S1 chain: S1' = max( fma(S1, c1 - E/smax, P), max(fma(S1, c1, P - E), 0) )
// S2 as U = S2/k2: U' = fma(U, c2, S1_old); clamp provably inactive in-scan.
// ---------------------------------------------------------------------------
__global__ __launch_bounds__(32, 1)
void pass1_kernel(const float2* __restrict__ F2,   // forcings [T, CELLS]
                  const float2* __restrict__ S02,  // initial states [CELLS]
                  const float4* __restrict__ P4)   // params [CELLS]
{
    const int cell = blockIdx.x * 32 + threadIdx.x;

    const float4 u = P4[cell];
    const float smax = 10.0f  + 490.0f  * u.x;
    const float k1   = 0.01f  + 0.89f   * u.y;
    const float k2   = 0.001f + 0.199f  * u.z;
    const float kb   = 0.001f + 0.099f  * u.w;

    const float inv  = 1.0f / smax;
    const float ninv = -inv;
    const float c1   = 1.0f - k1 - k2;
    const float c2   = 1.0f - kb;

    float2 s = S02[cell];
    float S1 = s.x;
    float U  = s.y / k2;          // S2 = k2 * U

    const float2* __restrict__ F = F2 + cell;

#define LOADC(buf, ci)                                           \
    do {                                                         \
        const float2* Fp = F + (size_t)(ci) * CHUNK * CELLS;     \
        _Pragma("unroll")                                        \
        for (int i = 0; i < CHUNK; i++)                          \
            (buf)[i] = Fp[i * CELLS];                            \
    } while (0)

#define PROC_LOAD(pbuf, pci, lbuf, lci_raw)                      \
    do {                                                         \
        const int lci = ((lci_raw) < NCHUNK) ? (lci_raw)         \
                                             : (NCHUNK - 1);     \
        const float2* Fp = F + (size_t)lci * CHUNK * CELLS;      \
        _Pragma("unroll")                                        \
        for (int i = 0; i < CHUNK; i++) {                        \
            (lbuf)[i] = Fp[i * CELLS];                           \
            const float Pf  = (pbuf)[i].x;                       \
            const float Ef  = (pbuf)[i].y;                       \
            const float caa = fmaf(ninv, Ef, c1);                \
            const float pme = Pf - Ef;                           \
            const float t1  = fmaf(S1, caa, Pf);                 \
            const float t2  = fmaf(S1, c1, pme);                 \
            U = fmaf(U, c2, S1);          /* old S1 */           \
            const float m = fmaxf(t2, 0.0f);                     \
            S1 = fmaxf(t1, m);                                   \
        }                                                        \
        if ((pci) != NCHUNK - 1)                                 \
            g_bound[((pci) + 1) * CELLS + cell] =                \
                make_float2(S1, k2 * U);                         \
    } while (0)

    float2 bufA[CHUNK], bufB[CHUNK], bufC[CHUNK], bufD[CHUNK];

    LOADC(bufA, 0);
    LOADC(bufB, 1);
    LOADC(bufC, 2);

#pragma unroll 1
    for (int c = 0; c < NCHUNK; c += 4) {
        PROC_LOAD(bufA, c,     bufD, c + 3);
        PROC_LOAD(bufB, c + 1, bufA, c + 4);
        PROC_LOAD(bufC, c + 2, bufB, c + 5);
        PROC_LOAD(bufD, c + 3, bufC, c + 6);
    }
#undef LOADC
#undef PROC_LOAD
}

// ---------------------------------------------------------------------------
// Pass 2: parallel segment replay. One thread = (cell, segment).
// Reference-faithful arithmetic. At its memory roofline (~21us).
// ---------------------------------------------------------------------------
__global__ __launch_bounds__(256)
void pass2_kernel(const float2* __restrict__ F2,   // forcings [T, CELLS]
                  const float2* __restrict__ S02,  // initial states [CELLS]
                  const float4* __restrict__ P4,   // params [CELLS]
                  float4* __restrict__ FX4,        // fluxes [T, CELLS]
                  float2* __restrict__ ST2)        // states [T, CELLS]
{
    const int cell = blockIdx.x * 256 + threadIdx.x;
    const int seg  = blockIdx.y;
    const int t0   = seg * SEGLEN;

    const float4 u = P4[cell];
    const float smax = 10.0f  + 490.0f  * u.x;
    const float k1   = 0.01f  + 0.89f   * u.y;
    const float k2   = 0.001f + 0.199f  * u.z;
    const float kb   = 0.001f + 0.099f  * u.w;
    const float inv  = 1.0f / smax;

    float2 s = (seg == 0) ? S02[cell] : g_bound[seg * CELLS + cell];
    float S1 = s.x, S2 = s.y;

    const float2* __restrict__ F  = F2  + (size_t)t0 * CELLS + cell;
    float4*       __restrict__ FX = FX4 + (size_t)t0 * CELLS + cell;
    float2*       __restrict__ ST = ST2 + (size_t)t0 * CELLS + cell;

#pragma unroll 8
    for (int i = 0; i < SEGLEN; i++) {
        const float2 f  = F[i * CELLS];
        const float P   = f.x;
        const float PET = f.y;

        const float frac = fminf(S1 * inv, 1.0f);   // S1 >= 0 always
        const float et   = PET * frac;
        const float q1   = k1 * S1;
        const float perc = k2 * S1;
        const float qb   = kb * S2;

        FX[i * CELLS] = make_float4(et, q1, perc, qb);

        S1 = fmaxf(S1 + P - et - q1 - perc, 0.0f);
        S2 = fmaxf(S2 + perc - qb, 0.0f);

        ST[i * CELLS] = make_float2(S1, S2);
    }
}

// ---------------------------------------------------------------------------
// Overlap resources (stream + events), created once at program init.
// No device allocations. Falls back to serial warm->pass1->pass2 if needed.
// ---------------------------------------------------------------------------
namespace {
struct OverlapRes {
    cudaStream_t sB = nullptr;
    cudaEvent_t  ev0 = nullptr, evW = nullptr;
    bool ok = false;
    OverlapRes() {
        if (cudaStreamCreateWithFlags(&sB, cudaStreamNonBlocking) != cudaSuccess)
            return;
        if (cudaEventCreateWithFlags(&ev0, cudaEventDisableTiming) != cudaSuccess)
            return;
        if (cudaEventCreateWithFlags(&evW, cudaEventDisableTiming) != cudaSuccess)
            return;
        ok = true;
    }
};
OverlapRes g_res;
}

extern "C" void kernel_launch(void* const* d_in, const int* in_sizes, int n_in,
                              void* d_out, int out_size)
{
    const float* forcings = (const float*)d_in[0];   // [T,B,H,2]
    const float* states0  = (const float*)d_in[1];   // [B,H,2]
    const float* params   = (const float*)d_in[2];   // [B,H,4]

    float* out = (float*)d_out;
    float* fluxes_out = out;                                   // [T,B,H,4]
    float* states_out = out + (size_t)TT * CELLS * 4;          // [T,B,H,2]

    const float2* F2  = reinterpret_cast<const float2*>(forcings);
    const float2* S02 = reinterpret_cast<const float2*>(states0);
    const float4* P4  = reinterpret_cast<const float4*>(params);
    const float4* F4  = reinterpret_cast<const float4*>(forcings);

    if (g_res.ok) {
        // Fork: throttled warm on stream B, concurrent with pass1.
        cudaEventRecord(g_res.ev0, 0);
        cudaStreamWaitEvent(g_res.sB, g_res.ev0, 0);
        warm_kernel<<<WARMBLK, 256, 0, g_res.sB>>>(F4);
        cudaEventRecord(g_res.evW, g_res.sB);

        pass1_kernel<<<CELLS / 32, 32>>>(F2, S02, P4);

        // Join before pass2.
        cudaStreamWaitEvent(0, g_res.evW, 0);
        pass2_kernel<<<dim3(CELLS / 256, NSEG), 256>>>(
            F2, S02, P4,
            reinterpret_cast<float4*>(fluxes_out),
            reinterpret_cast<float2*>(states_out));
    } else {
        // Serial fallback (round-13 behavior).
        warm_kernel<<<WARMBLK, 256>>>(F4);
        pass1_kernel<<<CELLS / 32, 32>>>(F2, S02, P4);
        pass2_kernel<<<dim3(CELLS / 256, NSEG), 256>>>(
            F2, S02, P4,
            reinterpret_cast<float4*>(fluxes_out),
            reinterpret_cast<float2*>(states_out));
    }
}